// round 3
// baseline (speedup 1.0000x reference)
#include <cuda_runtime.h>
#include <stdint.h>

#define RMS_EPS 1e-6f
#define NUM_SMS 152
#define CTAS_PER_SM 4
#define GRID_CTAS (NUM_SMS * CTAS_PER_SM)

__global__ void __launch_bounds__(512, CTAS_PER_SM)
dequant_add_rmsnorm_quant_kernel(const int*   __restrict__ x,
                                 const float* __restrict__ residual,
                                 const float* __restrict__ scale,
                                 const float* __restrict__ weight,
                                 const float* __restrict__ dqs,
                                 float*       __restrict__ out_q,   // output 0 (quantized values as f32)
                                 float*       __restrict__ res_out, // output 1 (res_new as f32)
                                 int T, int H)
{
    const int tid = threadIdx.x;
    const int i0  = tid << 3;  // 8 elements per thread
    const int wid = tid >> 5, lid = tid & 31;

    __shared__ float wsum[16];
    __shared__ float inv_s;

    const float gdqs = __ldg(dqs);

    // weight slice for this thread — L1-resident after first row
    const float4 wa = *(const float4*)(weight + i0);
    const float4 wb = *(const float4*)(weight + i0 + 4);
    const float w[8] = {wa.x, wa.y, wa.z, wa.w, wb.x, wb.y, wb.z, wb.w};

    for (int row = blockIdx.x; row < T; row += GRID_CTAS) {
        const size_t base = (size_t)row * (size_t)H;
        const float s = __ldg(scale + row) * gdqs;

        // ---- front-batched 128-bit streaming loads ----
        const int4   xa = __ldcs((const int4*)  (x        + base + i0));
        const int4   xb = __ldcs((const int4*)  (x        + base + i0 + 4));
        const float4 ra = __ldcs((const float4*)(residual + base + i0));
        const float4 rb = __ldcs((const float4*)(residual + base + i0 + 4));

        float r[8];
        r[0] = fmaf((float)xa.x, s, ra.x);
        r[1] = fmaf((float)xa.y, s, ra.y);
        r[2] = fmaf((float)xa.z, s, ra.z);
        r[3] = fmaf((float)xa.w, s, ra.w);
        r[4] = fmaf((float)xb.x, s, rb.x);
        r[5] = fmaf((float)xb.y, s, rb.y);
        r[6] = fmaf((float)xb.z, s, rb.z);
        r[7] = fmaf((float)xb.w, s, rb.w);

        // res_new (output 1) while hot in registers — streaming store
        __stcs((float4*)(res_out + base + i0),     make_float4(r[0], r[1], r[2], r[3]));
        __stcs((float4*)(res_out + base + i0 + 4), make_float4(r[4], r[5], r[6], r[7]));

        float ss = 0.f;
        #pragma unroll
        for (int i = 0; i < 8; i++) ss = fmaf(r[i], r[i], ss);

        // ---- block reduction: 16 warps ----
        #pragma unroll
        for (int o = 16; o > 0; o >>= 1)
            ss += __shfl_xor_sync(0xFFFFFFFFu, ss, o);

        if (lid == 0) wsum[wid] = ss;
        __syncthreads();
        if (tid < 32) {
            float v = (tid < 16) ? wsum[tid] : 0.f;
            #pragma unroll
            for (int o = 8; o > 0; o >>= 1)
                v += __shfl_xor_sync(0xFFFFFFFFu, v, o);
            if (tid == 0) inv_s = 1.0f / sqrtf(v / (float)H + RMS_EPS);
        }
        __syncthreads();
        const float inv = inv_s;

        // ---- normalize, weight, round-half-even, saturate ----
        float q[8];
        #pragma unroll
        for (int i = 0; i < 8; i++) {
            float v = rintf(r[i] * inv * w[i]);      // jnp.round = half-to-even
            q[i] = fminf(fmaxf(v, -128.f), 127.f);   // clip; int8 value as f32
        }
        __stcs((float4*)(out_q + base + i0),     make_float4(q[0], q[1], q[2], q[3]));
        __stcs((float4*)(out_q + base + i0 + 4), make_float4(q[4], q[5], q[6], q[7]));
    }
}

extern "C" void kernel_launch(void* const* d_in, const int* in_sizes, int n_in,
                              void* d_out, int out_size)
{
    const int*   x        = (const int*)  d_in[0];
    const float* residual = (const float*)d_in[1];
    const float* scale    = (const float*)d_in[2];
    const float* weight   = (const float*)d_in[3];
    const float* dqs      = (const float*)d_in[4];

    const int T  = in_sizes[2];   // scale is [T]
    const int H  = in_sizes[3];   // weight is [H]

    // Outputs cast to f32 and concatenated: [quant | res_new]
    float* out_q   = (float*)d_out;
    float* res_out = (float*)d_out + (size_t)out_size / 2;

    const int threads = H / 8;   // H=4096 -> 512
    dequant_add_rmsnorm_quant_kernel<<<GRID_CTAS, threads>>>(
        x, residual, scale, weight, dqs, out_q, res_out, T, H);
}

// round 4
// speedup vs baseline: 1.1384x; 1.1384x over previous
#include <cuda_runtime.h>
#include <stdint.h>

#define RMS_EPS 1e-6f

__global__ void __launch_bounds__(512)
dequant_add_rmsnorm_quant_kernel(const int*   __restrict__ x,
                                 const float* __restrict__ residual,
                                 const float* __restrict__ scale,
                                 const float* __restrict__ weight,
                                 const float* __restrict__ dqs,
                                 float*       __restrict__ out_q,   // output 0 (quantized values as f32)
                                 float*       __restrict__ res_out, // output 1 (res_new as f32)
                                 int H)
{
    const int row = blockIdx.x;
    const int tid = threadIdx.x;
    const size_t base = (size_t)row * (size_t)H;
    const int i0 = tid << 3;  // 8 elements per thread
    const int wid = tid >> 5, lid = tid & 31;

    const float s = __ldg(scale + row) * __ldg(dqs);

    // ---- front-batched 128-bit streaming loads (evict-first) ----
    const int4   xa = __ldcs((const int4*)  (x        + base + i0));
    const int4   xb = __ldcs((const int4*)  (x        + base + i0 + 4));
    const float4 ra = __ldcs((const float4*)(residual + base + i0));
    const float4 rb = __ldcs((const float4*)(residual + base + i0 + 4));

    float r[8];
    r[0] = fmaf((float)xa.x, s, ra.x);
    r[1] = fmaf((float)xa.y, s, ra.y);
    r[2] = fmaf((float)xa.z, s, ra.z);
    r[3] = fmaf((float)xa.w, s, ra.w);
    r[4] = fmaf((float)xb.x, s, rb.x);
    r[5] = fmaf((float)xb.y, s, rb.y);
    r[6] = fmaf((float)xb.z, s, rb.z);
    r[7] = fmaf((float)xb.w, s, rb.w);

    // res_new (output 1) while hot in registers — write-through streaming store
    __stwt((float4*)(res_out + base + i0),     make_float4(r[0], r[1], r[2], r[3]));
    __stwt((float4*)(res_out + base + i0 + 4), make_float4(r[4], r[5], r[6], r[7]));

    float ss = 0.f;
    #pragma unroll
    for (int i = 0; i < 8; i++) ss = fmaf(r[i], r[i], ss);

    // ---- block reduction: warp reduce -> smem -> single barrier ->
    //      every warp redundantly reduces the 16 partials (no 2nd barrier) ----
    #pragma unroll
    for (int o = 16; o > 0; o >>= 1)
        ss += __shfl_xor_sync(0xFFFFFFFFu, ss, o);

    __shared__ float wsum[16];
    if (lid == 0) wsum[wid] = ss;
    __syncthreads();

    float v = wsum[lid & 15];   // lanes 0-15 & 16-31 read same addrs (broadcast)
    #pragma unroll
    for (int o = 8; o > 0; o >>= 1)
        v += __shfl_xor_sync(0xFFFFFFFFu, v, o);
    const float inv = 1.0f / sqrtf(v / (float)H + RMS_EPS);   // exact R2 math

    // ---- normalize, weight, round-half-even, saturate ----
    const float4 wa = *(const float4*)(weight + i0);
    const float4 wb = *(const float4*)(weight + i0 + 4);
    const float w[8] = {wa.x, wa.y, wa.z, wa.w, wb.x, wb.y, wb.z, wb.w};

    float q[8];
    #pragma unroll
    for (int i = 0; i < 8; i++) {
        float t = rintf(r[i] * inv * w[i]);      // jnp.round = half-to-even
        q[i] = fminf(fmaxf(t, -128.f), 127.f);   // clip; int8 value as f32
    }
    __stwt((float4*)(out_q + base + i0),     make_float4(q[0], q[1], q[2], q[3]));
    __stwt((float4*)(out_q + base + i0 + 4), make_float4(q[4], q[5], q[6], q[7]));
}

extern "C" void kernel_launch(void* const* d_in, const int* in_sizes, int n_in,
                              void* d_out, int out_size)
{
    const int*   x        = (const int*)  d_in[0];
    const float* residual = (const float*)d_in[1];
    const float* scale    = (const float*)d_in[2];
    const float* weight   = (const float*)d_in[3];
    const float* dqs      = (const float*)d_in[4];

    const int T  = in_sizes[2];   // scale is [T]
    const int H  = in_sizes[3];   // weight is [H]

    // Outputs cast to f32 and concatenated: [quant | res_new]
    float* out_q   = (float*)d_out;
    float* res_out = (float*)d_out + (size_t)out_size / 2;

    const int threads = H / 8;   // H=4096 -> 512
    dequant_add_rmsnorm_quant_kernel<<<T, threads>>>(
        x, residual, scale, weight, dqs, out_q, res_out, H);
}

// round 5
// speedup vs baseline: 1.1592x; 1.0183x over previous
#include <cuda_runtime.h>
#include <stdint.h>

#define RMS_EPS 1e-6f

__global__ void __launch_bounds__(512)
dequant_add_rmsnorm_quant_kernel(const int*   __restrict__ x,
                                 const float* __restrict__ residual,
                                 const float* __restrict__ scale,
                                 const float* __restrict__ weight,
                                 const float* __restrict__ dqs,
                                 float*       __restrict__ out_q,   // output 0 (quantized values as f32)
                                 float*       __restrict__ res_out, // output 1 (res_new as f32)
                                 int H)
{
    const int row = blockIdx.x;
    const int tid = threadIdx.x;
    const size_t base = (size_t)row * (size_t)H;
    const int i0 = tid << 3;  // 8 elements per thread

    const float s = __ldg(scale + row) * __ldg(dqs);

    // ---- front-batched 128-bit loads (MLP_p1 = 4) ----
    const int4   xa = *(const int4*)  (x        + base + i0);
    const int4   xb = *(const int4*)  (x        + base + i0 + 4);
    const float4 ra = *(const float4*)(residual + base + i0);
    const float4 rb = *(const float4*)(residual + base + i0 + 4);

    float r[8];
    r[0] = fmaf((float)xa.x, s, ra.x);
    r[1] = fmaf((float)xa.y, s, ra.y);
    r[2] = fmaf((float)xa.z, s, ra.z);
    r[3] = fmaf((float)xa.w, s, ra.w);
    r[4] = fmaf((float)xb.x, s, rb.x);
    r[5] = fmaf((float)xb.y, s, rb.y);
    r[6] = fmaf((float)xb.z, s, rb.z);
    r[7] = fmaf((float)xb.w, s, rb.w);

    // res_new (output 1) while hot in registers — default write-back store:
    // L2 absorbs/batches the write stream into full-line writebacks.
    *(float4*)(res_out + base + i0)     = make_float4(r[0], r[1], r[2], r[3]);
    *(float4*)(res_out + base + i0 + 4) = make_float4(r[4], r[5], r[6], r[7]);

    float ss = 0.f;
    #pragma unroll
    for (int i = 0; i < 8; i++) ss = fmaf(r[i], r[i], ss);

    // ---- block reduction: 16 warps (exact R2 structure) ----
    #pragma unroll
    for (int o = 16; o > 0; o >>= 1)
        ss += __shfl_xor_sync(0xFFFFFFFFu, ss, o);

    __shared__ float wsum[16];
    __shared__ float inv_s;
    const int wid = tid >> 5, lid = tid & 31;
    if (lid == 0) wsum[wid] = ss;
    __syncthreads();
    if (tid < 32) {
        float v = (tid < 16) ? wsum[tid] : 0.f;
        #pragma unroll
        for (int o = 8; o > 0; o >>= 1)
            v += __shfl_xor_sync(0xFFFFFFFFu, v, o);
        if (tid == 0) inv_s = 1.0f / sqrtf(v / (float)H + RMS_EPS);
    }
    __syncthreads();
    const float inv = inv_s;

    // ---- normalize, weight, round-half-even, saturate ----
    const float4 wa = *(const float4*)(weight + i0);
    const float4 wb = *(const float4*)(weight + i0 + 4);
    const float w[8] = {wa.x, wa.y, wa.z, wa.w, wb.x, wb.y, wb.z, wb.w};

    float q[8];
    #pragma unroll
    for (int i = 0; i < 8; i++) {
        float t = rintf(r[i] * inv * w[i]);      // jnp.round = half-to-even
        q[i] = fminf(fmaxf(t, -128.f), 127.f);   // clip; int8 value as f32
    }
    *(float4*)(out_q + base + i0)     = make_float4(q[0], q[1], q[2], q[3]);
    *(float4*)(out_q + base + i0 + 4) = make_float4(q[4], q[5], q[6], q[7]);
}

extern "C" void kernel_launch(void* const* d_in, const int* in_sizes, int n_in,
                              void* d_out, int out_size)
{
    const int*   x        = (const int*)  d_in[0];
    const float* residual = (const float*)d_in[1];
    const float* scale    = (const float*)d_in[2];
    const float* weight   = (const float*)d_in[3];
    const float* dqs      = (const float*)d_in[4];

    const int T  = in_sizes[2];   // scale is [T]
    const int H  = in_sizes[3];   // weight is [H]

    // Outputs cast to f32 and concatenated: [quant | res_new]
    float* out_q   = (float*)d_out;
    float* res_out = (float*)d_out + (size_t)out_size / 2;

    const int threads = H / 8;   // H=4096 -> 512
    dequant_add_rmsnorm_quant_kernel<<<T, threads>>>(
        x, residual, scale, weight, dqs, out_q, res_out, H);
}